// round 2
// baseline (speedup 1.0000x reference)
#include <cuda_runtime.h>
#include <math.h>
#include <stdint.h>

#define B_   4
#define N_   4096
#define D_   64
#define K_   16
#define BN_  (B_*N_)            /* 16384 */
#define XE_SZ  (BN_*D_)         /* 1048576 */
#define EDGE_SZ (BN_*K_)        /* 262144 */

#define CLAMP_XV 1.0e6f
#define GUMBEL_MAX 3.1375f      /* log(-log(1e-10)) = 3.13656, + margin */

#define APITCH 136
#define SPITCH 132

__device__ float g_sq[BN_];

__device__ __forceinline__ float clampx(float v) {
    return fminf(fmaxf(v, -CLAMP_XV), CLAMP_XV);
}

/* Kernel 1: xe = clip(clip(x) @ W), row squared norms. One thread per row. */
__global__ __launch_bounds__(128) void embed_kernel(
    const float* __restrict__ x, const float* __restrict__ W,
    float* __restrict__ xe)
{
    __shared__ float Ws[64*64];
    int tid = threadIdx.x;
    for (int v = tid; v < 1024; v += 128)
        ((float4*)Ws)[v] = ((const float4*)W)[v];
    __syncthreads();

    int r = blockIdx.x * 128 + tid;
    float xv[64];
    const float4* xr = (const float4*)(x + (size_t)r * 64);
    #pragma unroll
    for (int q = 0; q < 16; q++) {
        float4 t = xr[q];
        xv[4*q+0] = clampx(t.x);
        xv[4*q+1] = clampx(t.y);
        xv[4*q+2] = clampx(t.z);
        xv[4*q+3] = clampx(t.w);
    }
    float sq = 0.f;
    float4* outr = (float4*)(xe + (size_t)r * 64);
    #pragma unroll
    for (int jg = 0; jg < 8; jg++) {
        float acc[8];
        #pragma unroll
        for (int c = 0; c < 8; c++) acc[c] = 0.f;
        #pragma unroll 8
        for (int k = 0; k < 64; k++) {
            float a = xv[k];
            float4 w0 = ((const float4*)Ws)[k*16 + jg*2];
            float4 w1 = ((const float4*)Ws)[k*16 + jg*2 + 1];
            acc[0] = fmaf(a, w0.x, acc[0]);
            acc[1] = fmaf(a, w0.y, acc[1]);
            acc[2] = fmaf(a, w0.z, acc[2]);
            acc[3] = fmaf(a, w0.w, acc[3]);
            acc[4] = fmaf(a, w1.x, acc[4]);
            acc[5] = fmaf(a, w1.y, acc[5]);
            acc[6] = fmaf(a, w1.z, acc[6]);
            acc[7] = fmaf(a, w1.w, acc[7]);
        }
        float e0 = clampx(acc[0]), e1 = clampx(acc[1]);
        float e2 = clampx(acc[2]), e3 = clampx(acc[3]);
        float e4 = clampx(acc[4]), e5 = clampx(acc[5]);
        float e6 = clampx(acc[6]), e7 = clampx(acc[7]);
        outr[jg*2]   = make_float4(e0, e1, e2, e3);
        outr[jg*2+1] = make_float4(e4, e5, e6, e7);
        sq = fmaf(e0, e0, sq); sq = fmaf(e1, e1, sq);
        sq = fmaf(e2, e2, sq); sq = fmaf(e3, e3, sq);
        sq = fmaf(e4, e4, sq); sq = fmaf(e5, e5, sq);
        sq = fmaf(e6, e6, sq); sq = fmaf(e7, e7, sq);
    }
    g_sq[r] = sq;
}

/* Kernel 2: per-CTA 128 rows, 512 threads (16 warps).
   Tiled 128x128x64 fp32 GEMM (per-thread 4x8) -> SMEM scores;
   4 threads/row float4 scan with register-resident sorted top-16.
   Gumbel term evaluated only for candidates passing the conservative
   distance-space threshold thrd = (tv[15]+GUMBEL_MAX)/scale. */
__global__ __launch_bounds__(512, 1) void topk_kernel(
    const float* __restrict__ xe, const float* __restrict__ noise,
    const float* __restrict__ temperature, float* __restrict__ out)
{
    extern __shared__ float smem[];
    float* A   = smem;                    /* [64][APITCH] k-major, i inner */
    float* Bt  = A  + 64*APITCH;          /* [64][APITCH] */
    float* S   = Bt + 64*APITCH;          /* [128][SPITCH] */
    float* sqA = S  + 128*SPITCH;         /* [128] */
    float* sqB = sqA + 128;               /* [128] */

    int tid = threadIdx.x;
    int tx = tid & 15, ty = tid >> 4;     /* GEMM: cols tx*8, rows ty*4 */
    int R0 = blockIdx.x * 128;
    int batchBase = R0 & ~(N_-1);

    /* load + transpose the i-tile once (512 threads, 4 vec4/thread) */
    #pragma unroll
    for (int it = 0; it < 4; it++) {
        int v = tid + 512*it;
        int i = v >> 4, k4 = v & 15;
        float4 t = ((const float4*)(xe + (size_t)(R0+i)*64))[k4];
        A[(4*k4+0)*APITCH + i] = t.x;
        A[(4*k4+1)*APITCH + i] = t.y;
        A[(4*k4+2)*APITCH + i] = t.z;
        A[(4*k4+3)*APITCH + i] = t.w;
    }
    if (tid < 128) sqA[tid] = g_sq[R0 + tid];

    float scale = expf(fminf(fmaxf(*temperature, -5.f), 5.f));
    float invScale = 1.0f / scale;

    float tv[16]; int ti[16];
    const float INF = __int_as_float(0x7f800000);
    #pragma unroll
    for (int s = 0; s < 16; s++) { tv[s] = INF; ti[s] = 0; }

    int r = tid >> 2, q = tid & 3;        /* scan: row r, col-quarter q */
    size_t noiseRow = (size_t)(R0 + r) * N_;
    float thrd = INF;                     /* (tv[15]+GMAX)*invScale, distance space */
    float sqr;

    for (int jt = 0; jt < 32; jt++) {
        __syncthreads();   /* previous scan done before Bt overwrite */
        int J0 = batchBase + jt*128;
        #pragma unroll
        for (int it = 0; it < 4; it++) {
            int v = tid + 512*it;
            int i = v >> 4, k4 = v & 15;
            float4 t = ((const float4*)(xe + (size_t)(J0+i)*64))[k4];
            Bt[(4*k4+0)*APITCH + i] = t.x;
            Bt[(4*k4+1)*APITCH + i] = t.y;
            Bt[(4*k4+2)*APITCH + i] = t.z;
            Bt[(4*k4+3)*APITCH + i] = t.w;
        }
        if (tid < 128) sqB[tid] = g_sq[J0 + tid];
        __syncthreads();

        /* 4x8 register-blocked fp32 GEMM */
        float acc[4][8];
        #pragma unroll
        for (int ii = 0; ii < 4; ii++)
            #pragma unroll
            for (int jj = 0; jj < 8; jj++) acc[ii][jj] = 0.f;

        #pragma unroll 4
        for (int k = 0; k < 64; k++) {
            float4 a0 = *(const float4*)(A + k*APITCH + ty*4);
            float4 b0 = *(const float4*)(Bt + k*APITCH + tx*8);
            float4 b1 = *(const float4*)(Bt + k*APITCH + tx*8 + 4);
            float av[4] = {a0.x,a0.y,a0.z,a0.w};
            float bv[8] = {b0.x,b0.y,b0.z,b0.w,b1.x,b1.y,b1.z,b1.w};
            #pragma unroll
            for (int ii = 0; ii < 4; ii++)
                #pragma unroll
                for (int jj = 0; jj < 8; jj++)
                    acc[ii][jj] = fmaf(av[ii], bv[jj], acc[ii][jj]);
        }
        #pragma unroll
        for (int ii = 0; ii < 4; ii++) {
            float* sp = S + (ty*4+ii)*SPITCH + tx*8;
            *(float4*)sp       = make_float4(acc[ii][0],acc[ii][1],acc[ii][2],acc[ii][3]);
            *(float4*)(sp + 4) = make_float4(acc[ii][4],acc[ii][5],acc[ii][6],acc[ii][7]);
        }
        __syncthreads();

        /* scan: 4 threads per row, 32 cols each, float4 */
        const float* Srow = S + r*SPITCH + q*32;
        const float* sqBp = sqB + q*32;
        sqr = sqA[r];
        int jbase = jt*128 + q*32;
        #pragma unroll
        for (int jj = 0; jj < 32; jj += 4) {
            float4 dot = *(const float4*)(Srow + jj);
            float4 sb  = *(const float4*)(sqBp + jj);
            float d0 = fminf(fmaxf(fmaf(dot.x, -2.f, sqr + sb.x), 0.f), 1e10f);
            float d1 = fminf(fmaxf(fmaf(dot.y, -2.f, sqr + sb.y), 0.f), 1e10f);
            float d2 = fminf(fmaxf(fmaf(dot.z, -2.f, sqr + sb.z), 0.f), 1e10f);
            float d3 = fminf(fmaxf(fmaf(dot.w, -2.f, sqr + sb.w), 0.f), 1e10f);
            float m = fminf(fminf(d0, d1), fminf(d2, d3));
            if (m < thrd) {
                float dd[4] = {d0, d1, d2, d3};
                #pragma unroll
                for (int c = 0; c < 4; c++) {
                    if (dd[c] < thrd) {
                        int jl = jbase + jj + c;
                        float u = noise[noiseRow + jl];
                        float lq = dd[c] * scale - logf(-logf(u));
                        if (lq < tv[15]) {
                            float v = lq; int id = jl;
                            #pragma unroll
                            for (int s = 0; s < 16; s++) {
                                if (v < tv[s]) {
                                    float tmpv = tv[s]; tv[s] = v; v = tmpv;
                                    int   tmpi = ti[s]; ti[s] = id; id = tmpi;
                                }
                            }
                            thrd = (tv[15] + GUMBEL_MAX) * invScale;
                        }
                    }
                }
            }
        }
    }

    __syncthreads();
    /* dump the 4 per-thread sorted lists; reuse S region */
    float* vbuf = S;                       /* [128][64] */
    int*   ibuf = (int*)(S + 128*64);      /* [128][64] */
    #pragma unroll
    for (int s = 0; s < 16; s++) {
        vbuf[r*64 + q*16 + s] = tv[s];
        ibuf[r*64 + q*16 + s] = ti[s];
    }
    __syncthreads();
    if (q == 0) {
        const float* vr = vbuf + r*64;
        const int*   ir = ibuf + r*64;
        int p[4] = {0, 16, 32, 48};
        int gr = R0 + r;
        size_t eoff = (size_t)gr * K_;
        #pragma unroll
        for (int s = 0; s < 16; s++) {
            float bv = vr[p[0]]; int bi = ir[p[0]]; int bq = 0;
            #pragma unroll
            for (int l = 1; l < 4; l++) {
                float cv = vr[p[l]]; int ci = ir[p[l]];
                if (cv < bv || (cv == bv && ci < bi)) { bv = cv; bi = ci; bq = l; }
            }
            p[bq]++;
            out[XE_SZ + eoff + s]              = (float)gr;
            out[XE_SZ + EDGE_SZ + eoff + s]    = (float)(batchBase + bi);
            out[XE_SZ + 2*EDGE_SZ + eoff + s]  = fminf(fmaxf(bv, -1e10f), 0.f);
        }
    }
}

extern "C" void kernel_launch(void* const* d_in, const int* in_sizes, int n_in,
                              void* d_out, int out_size)
{
    (void)out_size;
    const float *x = nullptr, *W = nullptr, *temp = nullptr, *noise = nullptr;
    for (int i = 0; i < n_in; i++) {
        int s = in_sizes[i];
        if (s == 1)               temp  = (const float*)d_in[i];
        else if (s == D_*D_)      W     = (const float*)d_in[i];
        else if (s == BN_*D_)     x     = (const float*)d_in[i];
        else                      noise = (const float*)d_in[i];
    }
    float* out = (float*)d_out;

    embed_kernel<<<128, 128>>>(x, W, out);

    int smemBytes = (64*APITCH*2 + 128*SPITCH + 256) * 4;  /* 138240 B */
    cudaFuncSetAttribute(topk_kernel,
                         cudaFuncAttributeMaxDynamicSharedMemorySize, smemBytes);
    topk_kernel<<<128, 512, smemBytes>>>(out, noise, temp, out);
}

// round 3
// speedup vs baseline: 1.4132x; 1.4132x over previous
#include <cuda_runtime.h>
#include <math.h>
#include <stdint.h>

#define B_   4
#define N_   4096
#define D_   64
#define K_   16
#define BN_  (B_*N_)            /* 16384 */
#define XE_SZ  (BN_*D_)         /* 1048576 */
#define EDGE_SZ (BN_*K_)        /* 262144 */

#define CLAMP_XV 1.0e6f
#define GUMBEL_MAX 3.1375f      /* log(-log(1e-10)) = 3.13656, + margin */

#define APITCH 128              /* floats; row term vanishes mod 32 banks */
#define SPITCH 144              /* floats; SPITCH % 32 == 16 -> conflict-free scan */

__device__ float g_sq[BN_];

__device__ __forceinline__ float clampx(float v) {
    return fminf(fmaxf(v, -CLAMP_XV), CLAMP_XV);
}

/* rotated column index for tile buffers: row kk, scalar col i (0..127).
   chunk' = (i/4 + kk/4) & 31.  Makes transpose-fill STS conflict-free and
   GEMM loads (contiguous chunks, broadcast rows) conflict-free. */
__device__ __forceinline__ int rotcol(int kk, int i) {
    return ((((i >> 2) + (kk >> 2)) & 31) << 2) | (i & 3);
}

/* Kernel 1: xe = clip(clip(x) @ W), row squared norms. One thread per row. */
__global__ __launch_bounds__(128) void embed_kernel(
    const float* __restrict__ x, const float* __restrict__ W,
    float* __restrict__ xe)
{
    __shared__ float Ws[64*64];
    int tid = threadIdx.x;
    for (int v = tid; v < 1024; v += 128)
        ((float4*)Ws)[v] = ((const float4*)W)[v];
    __syncthreads();

    int r = blockIdx.x * 128 + tid;
    float xv[64];
    const float4* xr = (const float4*)(x + (size_t)r * 64);
    #pragma unroll
    for (int q = 0; q < 16; q++) {
        float4 t = xr[q];
        xv[4*q+0] = clampx(t.x);
        xv[4*q+1] = clampx(t.y);
        xv[4*q+2] = clampx(t.z);
        xv[4*q+3] = clampx(t.w);
    }
    float sq = 0.f;
    float4* outr = (float4*)(xe + (size_t)r * 64);
    #pragma unroll
    for (int jg = 0; jg < 8; jg++) {
        float acc[8];
        #pragma unroll
        for (int c = 0; c < 8; c++) acc[c] = 0.f;
        #pragma unroll 8
        for (int k = 0; k < 64; k++) {
            float a = xv[k];
            float4 w0 = ((const float4*)Ws)[k*16 + jg*2];
            float4 w1 = ((const float4*)Ws)[k*16 + jg*2 + 1];
            acc[0] = fmaf(a, w0.x, acc[0]);
            acc[1] = fmaf(a, w0.y, acc[1]);
            acc[2] = fmaf(a, w0.z, acc[2]);
            acc[3] = fmaf(a, w0.w, acc[3]);
            acc[4] = fmaf(a, w1.x, acc[4]);
            acc[5] = fmaf(a, w1.y, acc[5]);
            acc[6] = fmaf(a, w1.z, acc[6]);
            acc[7] = fmaf(a, w1.w, acc[7]);
        }
        float e0 = clampx(acc[0]), e1 = clampx(acc[1]);
        float e2 = clampx(acc[2]), e3 = clampx(acc[3]);
        float e4 = clampx(acc[4]), e5 = clampx(acc[5]);
        float e6 = clampx(acc[6]), e7 = clampx(acc[7]);
        outr[jg*2]   = make_float4(e0, e1, e2, e3);
        outr[jg*2+1] = make_float4(e4, e5, e6, e7);
        sq = fmaf(e0, e0, sq); sq = fmaf(e1, e1, sq);
        sq = fmaf(e2, e2, sq); sq = fmaf(e3, e3, sq);
        sq = fmaf(e4, e4, sq); sq = fmaf(e5, e5, sq);
        sq = fmaf(e6, e6, sq); sq = fmaf(e7, e7, sq);
    }
    g_sq[r] = sq;
}

/* Kernel 2: per-CTA 128 rows, 512 threads.
   Conflict-free tiled 128x128x64 fp32 GEMM (per-thread 4x8, split-j) -> SMEM;
   q-interleaved conflict-free scan, parallel sorted top-16 insert,
   quad-shared pruning threshold. */
__global__ __launch_bounds__(512, 1) void topk_kernel(
    const float* __restrict__ xe, const float* __restrict__ noise,
    const float* __restrict__ temperature, float* __restrict__ out)
{
    extern __shared__ float smem[];
    float* A   = smem;                    /* [64][128] rotated k-major */
    float* Bt  = A  + 64*APITCH;          /* [64][128] rotated k-major */
    float* S   = Bt + 64*APITCH;          /* [128][SPITCH] */
    float* sqA = S  + 128*SPITCH;         /* [128] */
    float* sqB = sqA + 128;               /* [128] */

    int tid = threadIdx.x;
    int tx = tid & 15, ty = tid >> 4;     /* GEMM: rows ty*4, cols {tx*4, 64+tx*4} */
    int R0 = blockIdx.x * 128;
    int batchBase = R0 & ~(N_-1);

    /* fill A tile (rotated transpose), conflict-free STS */
    #pragma unroll
    for (int it = 0; it < 4; it++) {
        int v = tid + 512*it;
        int i = v >> 4, k4 = v & 15;
        float4 t = ((const float4*)(xe + (size_t)(R0+i)*64))[k4];
        A[(4*k4+0)*APITCH + rotcol(4*k4+0, i)] = t.x;
        A[(4*k4+1)*APITCH + rotcol(4*k4+1, i)] = t.y;
        A[(4*k4+2)*APITCH + rotcol(4*k4+2, i)] = t.z;
        A[(4*k4+3)*APITCH + rotcol(4*k4+3, i)] = t.w;
    }
    if (tid < 128) sqA[tid] = g_sq[R0 + tid];

    float scale = expf(fminf(fmaxf(*temperature, -5.f), 5.f));
    float invScale = 1.0f / scale;

    float tv[16]; int ti[16];
    const float INF = __int_as_float(0x7f800000);
    #pragma unroll
    for (int s = 0; s < 16; s++) { tv[s] = INF; ti[s] = 0; }

    int r = tid >> 2, q = tid & 3;        /* scan: row r, q-interleaved chunks */
    size_t noiseRow = (size_t)(R0 + r) * N_;

    for (int jt = 0; jt < 32; jt++) {
        __syncthreads();   /* previous scan done before Bt/sqB overwrite */
        int J0 = batchBase + jt*128;
        #pragma unroll
        for (int it = 0; it < 4; it++) {
            int v = tid + 512*it;
            int i = v >> 4, k4 = v & 15;
            float4 t = ((const float4*)(xe + (size_t)(J0+i)*64))[k4];
            Bt[(4*k4+0)*APITCH + rotcol(4*k4+0, i)] = t.x;
            Bt[(4*k4+1)*APITCH + rotcol(4*k4+1, i)] = t.y;
            Bt[(4*k4+2)*APITCH + rotcol(4*k4+2, i)] = t.z;
            Bt[(4*k4+3)*APITCH + rotcol(4*k4+3, i)] = t.w;
        }
        if (tid < 128) sqB[tid] = g_sq[J0 + tid];
        __syncthreads();

        /* 4x8 register-blocked fp32 GEMM, conflict-free LDS */
        float acc[4][8];
        #pragma unroll
        for (int ii = 0; ii < 4; ii++)
            #pragma unroll
            for (int jj = 0; jj < 8; jj++) acc[ii][jj] = 0.f;

        #pragma unroll 8
        for (int k = 0; k < 64; k++) {
            int R = k >> 2;
            float4 a0 = *(const float4*)(A  + k*APITCH + (((ty + R)      & 31) << 2));
            float4 b0 = *(const float4*)(Bt + k*APITCH + (((tx + R)      & 31) << 2));
            float4 b1 = *(const float4*)(Bt + k*APITCH + (((tx + 16 + R) & 31) << 2));
            float av[4] = {a0.x,a0.y,a0.z,a0.w};
            float bv[8] = {b0.x,b0.y,b0.z,b0.w,b1.x,b1.y,b1.z,b1.w};
            #pragma unroll
            for (int ii = 0; ii < 4; ii++)
                #pragma unroll
                for (int jj = 0; jj < 8; jj++)
                    acc[ii][jj] = fmaf(av[ii], bv[jj], acc[ii][jj]);
        }
        #pragma unroll
        for (int ii = 0; ii < 4; ii++) {
            float* sp = S + (ty*4+ii)*SPITCH;
            *(float4*)(sp + tx*4)      = make_float4(acc[ii][0],acc[ii][1],acc[ii][2],acc[ii][3]);
            *(float4*)(sp + 64 + tx*4) = make_float4(acc[ii][4],acc[ii][5],acc[ii][6],acc[ii][7]);
        }
        __syncthreads();

        /* row-wide threshold: min over the 4 quad threads of tv[15] */
        float t15 = tv[15];
        t15 = fminf(t15, __shfl_xor_sync(0xffffffffu, t15, 1));
        t15 = fminf(t15, __shfl_xor_sync(0xffffffffu, t15, 2));
        float thrd = (t15 + GUMBEL_MAX) * invScale;   /* distance-space prune */

        /* scan: 4 threads/row, q-interleaved float4 chunks (conflict-free) */
        const float* Srow = S + r*SPITCH;
        float sqr = sqA[r];
        #pragma unroll
        for (int jj = 0; jj < 8; jj++) {
            int coff = 16*jj + 4*q;
            float4 dot = *(const float4*)(Srow + coff);
            float4 sb  = *(const float4*)(sqB + coff);
            float d0 = fminf(fmaxf(fmaf(dot.x, -2.f, sqr + sb.x), 0.f), 1e10f);
            float d1 = fminf(fmaxf(fmaf(dot.y, -2.f, sqr + sb.y), 0.f), 1e10f);
            float d2 = fminf(fmaxf(fmaf(dot.z, -2.f, sqr + sb.z), 0.f), 1e10f);
            float d3 = fminf(fmaxf(fmaf(dot.w, -2.f, sqr + sb.w), 0.f), 1e10f);
            float m = fminf(fminf(d0, d1), fminf(d2, d3));
            if (m < thrd) {
                float dd[4] = {d0, d1, d2, d3};
                #pragma unroll
                for (int c = 0; c < 4; c++) {
                    if (dd[c] < thrd) {
                        int jl = jt*128 + coff + c;
                        float u = noise[noiseRow + jl];
                        float lq = fmaf(dd[c], scale, -logf(-logf(u)));
                        if (lq < tv[15]) {
                            /* parallel sorted insert (shift-register form) */
                            #pragma unroll
                            for (int s = 15; s >= 1; s--) {
                                bool shp  = lq < tv[s-1];
                                bool here = (lq < tv[s]) && !shp;
                                tv[s] = shp ? tv[s-1] : (here ? lq : tv[s]);
                                ti[s] = shp ? ti[s-1] : (here ? jl : ti[s]);
                            }
                            if (lq < tv[0]) { tv[0] = lq; ti[0] = jl; }
                            thrd = fminf(thrd, (tv[15] + GUMBEL_MAX) * invScale);
                        }
                    }
                }
            }
        }
    }

    __syncthreads();
    /* dump the 4 per-thread sorted lists; reuse S region */
    float* vbuf = S;                       /* [128][64] */
    int*   ibuf = (int*)(S + 128*64);      /* [128][64] */
    #pragma unroll
    for (int s = 0; s < 16; s++) {
        vbuf[r*64 + q*16 + s] = tv[s];
        ibuf[r*64 + q*16 + s] = ti[s];
    }
    __syncthreads();
    if (q == 0) {
        const float* vr = vbuf + r*64;
        const int*   ir = ibuf + r*64;
        int p[4] = {0, 16, 32, 48};
        int gr = R0 + r;
        size_t eoff = (size_t)gr * K_;
        #pragma unroll
        for (int s = 0; s < 16; s++) {
            float bv = vr[p[0]]; int bi = ir[p[0]]; int bq = 0;
            #pragma unroll
            for (int l = 1; l < 4; l++) {
                float cv = vr[p[l]]; int ci = ir[p[l]];
                if (cv < bv || (cv == bv && ci < bi)) { bv = cv; bi = ci; bq = l; }
            }
            p[bq]++;
            out[XE_SZ + eoff + s]              = (float)gr;
            out[XE_SZ + EDGE_SZ + eoff + s]    = (float)(batchBase + bi);
            out[XE_SZ + 2*EDGE_SZ + eoff + s]  = fminf(fmaxf(bv, -1e10f), 0.f);
        }
    }
}

extern "C" void kernel_launch(void* const* d_in, const int* in_sizes, int n_in,
                              void* d_out, int out_size)
{
    (void)out_size;
    const float *x = nullptr, *W = nullptr, *temp = nullptr, *noise = nullptr;
    for (int i = 0; i < n_in; i++) {
        int s = in_sizes[i];
        if (s == 1)               temp  = (const float*)d_in[i];
        else if (s == D_*D_)      W     = (const float*)d_in[i];
        else if (s == BN_*D_)     x     = (const float*)d_in[i];
        else                      noise = (const float*)d_in[i];
    }
    float* out = (float*)d_out;

    embed_kernel<<<128, 128>>>(x, W, out);

    int smemBytes = (64*APITCH*2 + 128*SPITCH + 256) * 4;  /* 140288 B */
    cudaFuncSetAttribute(topk_kernel,
                         cudaFuncAttributeMaxDynamicSharedMemorySize, smemBytes);
    topk_kernel<<<128, 512, smemBytes>>>(out, noise, temp, out);
}